// round 4
// baseline (speedup 1.0000x reference)
#include <cuda_runtime.h>
#include <cuda_bf16.h>

#define PH    16
#define PW    16
#define NM    16
#define HDIM  224
#define WDIM  224
#define CDIM  64
#define HW    (HDIM * WDIM)
#define NPH   (HDIM / PH)    // 14
#define NPW   (WDIM / PW)    // 14

// One WARP per 16x16 patch. No smem, no __syncthreads — warps fully decoupled
// so DRAM demand never pauses at a barrier.
// lane owns pixel-quads q0=lane, q1=lane+32  (quad q -> row q>>2, col (q&3)*4),
// i.e. byte offsets 16*lane and 16*lane+512 within the patch.
__global__ __launch_bounds__(128, 10)
void msp_dct_kernel(const float* __restrict__ x,
                    const float* __restrict__ bases,
                    float* __restrict__ out) {
    const int lane  = threadIdx.x & 31;
    const int gwarp = blockIdx.x * 4 + (threadIdx.x >> 5);   // 0..3135
    const int b     = gwarp / (NPH * NPW);
    const int pp    = gwarp - b * (NPH * NPW);
    const int ph    = pp / NPW;
    const int pw    = pp - ph * NPW;
    const int h0    = ph * PH;
    const int w0    = pw * PW;

    const int r0  = lane >> 2;          // rows r0 and r0+8
    const int col = (lane & 3) * 4;

    // ---- phase 1: channel sum, two independent accumulators ----
    const float* p0 = x + (size_t)b * CDIM * HW
                        + (size_t)(h0 + r0) * WDIM + (w0 + col);
    float4 a0 = make_float4(0.f, 0.f, 0.f, 0.f);
    float4 a1 = make_float4(0.f, 0.f, 0.f, 0.f);
    #pragma unroll 4
    for (int c = 0; c < CDIM; c++) {
        const float4 v0 = __ldcs(reinterpret_cast<const float4*>(p0 + (size_t)c * HW));
        const float4 v1 = __ldcs(reinterpret_cast<const float4*>(p0 + (size_t)c * HW + 8 * WDIM));
        a0.x += v0.x; a0.y += v0.y; a0.z += v0.z; a0.w += v0.w;
        a1.x += v1.x; a1.y += v1.y; a1.z += v1.z; a1.w += v1.w;
    }

    // ---- phase 2: DCT partials + full-warp xor reduce (all lanes get result) ----
    float part[NM];
    const float* bq0 = bases + lane * 4;          // quad q0 offset
    #pragma unroll
    for (int m = 0; m < NM; m++) {
        const float4 u0 = __ldg(reinterpret_cast<const float4*>(bq0 + m * 256));
        const float4 u1 = __ldg(reinterpret_cast<const float4*>(bq0 + m * 256 + 128));
        part[m] = a0.x * u0.x + a0.y * u0.y + a0.z * u0.z + a0.w * u0.w
                + a1.x * u1.x + a1.y * u1.y + a1.z * u1.z + a1.w * u1.w;
    }
    #pragma unroll
    for (int m = 0; m < NM; m++) {
        #pragma unroll
        for (int off = 16; off; off >>= 1)
            part[m] += __shfl_xor_sync(0xffffffffu, part[m], off);
        part[m] *= (1.0f / (float)CDIM);
    }

    // ---- phase 3: broadcast stores, same quad ownership ----
    float* o0 = out + (size_t)b * NM * HW
                    + (size_t)(h0 + r0) * WDIM + (w0 + col);
    #pragma unroll
    for (int m = 0; m < NM; m++) {
        const float4 vv = make_float4(part[m], part[m], part[m], part[m]);
        __stcs(reinterpret_cast<float4*>(o0 + (size_t)m * HW), vv);
        __stcs(reinterpret_cast<float4*>(o0 + (size_t)m * HW + 8 * WDIM), vv);
    }
}

extern "C" void kernel_launch(void* const* d_in, const int* in_sizes, int n_in,
                              void* d_out, int out_size) {
    const float* x     = (const float*)d_in[0];
    const float* bases = (const float*)d_in[1];
    float*       out   = (float*)d_out;
    // 3136 patches, 1 warp each, 4 warps per CTA
    msp_dct_kernel<<<784, 128>>>(x, bases, out);
}